// round 9
// baseline (speedup 1.0000x reference)
#include <cuda_runtime.h>
#include <cuda_fp16.h>
#include <cstdint>

// ============================================================================
// NestedMoEModel: softmax gate row-sums to 1 => gate path is a no-op.
// out[B, G*H] = x @ (sum_e W_exp)^T + sum_e b_exp
// Single GEMM M=32768, N=2048, K=256 via fp16 mma.sync (fp32 accumulate).
// PTX target is sm_103 (no 'a') -> tcgen05 unavailable; mma.sync path.
// R9: smem-free GEMM. Prep writes operands in mma-fragment layout; the GEMM
//     does coalesced LDG.128 straight into fragments (no cp.async, no ldsm,
//     no __syncthreads) -> zero warp lockstep, warps free-run.
// ============================================================================

#define DINLINE __device__ __forceinline__

static constexpr int Bsz = 32768;
static constexpr int Dsz = 256;     // K
static constexpr int NN  = 2048;    // G*H = output cols
static constexpr int M_TILE = 128;
static constexpr int N_TILE = 128;
static constexpr int THREADS = 128;                  // 4 warps, 2x2 grid of 64x64
static constexpr int KSTEPS = Dsz / 16;              // 16

// Fragment-layout operand buffers.
// g_Xa: [m16 block 0..2047][ks 0..15][lane 0..31] -> uint4 {a0,a1,a2,a3}
//   a0 = x[m_lo][k0..k0+1], a1 = x[m_hi][k0..], a2 = x[m_lo][k0+8..], a3 = x[m_hi][k0+8..]
//   m_lo = m16*16 + (lane>>2), m_hi = m_lo+8, k0 = ks*16 + (lane&3)*2   (fp16 pairs)
// g_Wb: [n16 block 0..127][ks][lane] -> uint4 {b_lo0,b_lo1,b_hi0,b_hi1}
//   b_lo0 = w[n_lo][k0..+1], b_lo1 = w[n_lo][k0+8..], b_hi* = same for n_hi = n_lo+8
__device__ __align__(128) uint4 g_Xa[(Bsz / 16) * KSTEPS * 32];   // 16MB
__device__ __align__(128) uint4 g_Wb[(NN  / 16) * KSTEPS * 32];   // 1MB
__device__ __align__(128) float g_bsum[NN];

// ---------------------------------------------------------------------------
// helpers
// ---------------------------------------------------------------------------
DINLINE uint32_t pack2(float lo, float hi) {
    __half2 h = __floats2half2_rn(lo, hi);
    return *(uint32_t*)&h;
}

DINLINE void mma16816(float* d, const uint32_t* a, uint32_t b0, uint32_t b1) {
    asm volatile(
        "mma.sync.aligned.m16n8k16.row.col.f32.f16.f16.f32 "
        "{%0,%1,%2,%3}, {%4,%5,%6,%7}, {%8,%9}, {%0,%1,%2,%3};"
        : "+f"(d[0]), "+f"(d[1]), "+f"(d[2]), "+f"(d[3])
        : "r"(a[0]), "r"(a[1]), "r"(a[2]), "r"(a[3]), "r"(b0), "r"(b1));
}

// ---------------------------------------------------------------------------
// Fused prep:
//  blocks [0,256):    Wsum (reduce 8 experts) -> g_Wb fragment layout; blocks
//                     [0,8) also compute bias sums.
//  blocks [256,4352): x -> g_Xa fragment layout (fp16), 1 uint4 per thread.
// ---------------------------------------------------------------------------
__global__ void __launch_bounds__(256)
prep_kernel(const float* __restrict__ X,
            const float* __restrict__ W_exp,
            const float* __restrict__ b_exp) {
    const int blk = blockIdx.x;
    const int tid = threadIdx.x;

    if (blk < 256) {
        // ---- W path: one uint4 fragment entry per thread ----
        const int entry = blk * 256 + tid;          // [0, 65536)
        const int n16  = entry >> 9;                // 0..127
        const int ks   = (entry >> 5) & 15;
        const int lane = entry & 31;
        const int n_lo = n16 * 16 + (lane >> 2);
        const int k0   = ks * 16 + (lane & 3) * 2;
        const int g    = n_lo >> 8;
        const int h_lo = n_lo & 255;

        float s[8];                                  // {lo,hi} x {k0,k0+1,k0+8,k0+9}
#pragma unroll
        for (int j = 0; j < 8; j++) s[j] = 0.f;
#pragma unroll
        for (int e = 0; e < 8; e++) {
            const float* we = W_exp + ((size_t)(g * 8 + e) * 256) * 256;
            float2 lo_a = *(const float2*)(we + (size_t)h_lo * 256 + k0);
            float2 lo_b = *(const float2*)(we + (size_t)h_lo * 256 + k0 + 8);
            float2 hi_a = *(const float2*)(we + (size_t)(h_lo + 8) * 256 + k0);
            float2 hi_b = *(const float2*)(we + (size_t)(h_lo + 8) * 256 + k0 + 8);
            s[0] += lo_a.x; s[1] += lo_a.y;
            s[2] += lo_b.x; s[3] += lo_b.y;
            s[4] += hi_a.x; s[5] += hi_a.y;
            s[6] += hi_b.x; s[7] += hi_b.y;
        }
        uint4 v;
        v.x = pack2(s[0], s[1]);   // b_lo, k0
        v.y = pack2(s[2], s[3]);   // b_lo, k0+8
        v.z = pack2(s[4], s[5]);   // b_hi, k0
        v.w = pack2(s[6], s[7]);   // b_hi, k0+8
        g_Wb[entry] = v;

        if (blk < 8) {
            // bias: n = blk*256 + tid
            float bs = 0.f;
#pragma unroll
            for (int e = 0; e < 8; e++)
                bs += b_exp[(blk * 8 + e) * 256 + tid];
            g_bsum[blk * 256 + tid] = bs;
        }
    } else {
        // ---- A path: one uint4 fragment entry per thread ----
        const int entry = (blk - 256) * 256 + tid;   // [0, 1048576)
        const int m16  = entry >> 9;                 // 0..2047
        const int ks   = (entry >> 5) & 15;
        const int lane = entry & 31;
        const int m_lo = m16 * 16 + (lane >> 2);
        const int k0   = ks * 16 + (lane & 3) * 2;

        const float* xr = X + (size_t)m_lo * 256 + k0;
        float2 lo_a = *(const float2*)(xr);
        float2 lo_b = *(const float2*)(xr + 8);
        float2 hi_a = *(const float2*)(xr + 8 * 256);
        float2 hi_b = *(const float2*)(xr + 8 * 256 + 8);

        uint4 v;
        v.x = pack2(lo_a.x, lo_a.y);   // a0: m_lo, k0
        v.y = pack2(hi_a.x, hi_a.y);   // a1: m_hi, k0
        v.z = pack2(lo_b.x, lo_b.y);   // a2: m_lo, k0+8
        v.w = pack2(hi_b.x, hi_b.y);   // a3: m_hi, k0+8
        g_Xa[entry] = v;
    }
}
static constexpr int PREP_BLOCKS = 256 + (Bsz / 16) * KSTEPS * 32 / 256;  // 4352

// ---------------------------------------------------------------------------
// GEMM: out = Xa @ Wb^T + bsum.  No smem, no syncs.
// CTA 128x128, 128 threads (4 warps, 2x2 grid of 64x64). 2 CTAs/SM (regs).
// Per warp per k-step: 8 coalesced LDG.128 (double-buffered) + 32 MMAs.
// ---------------------------------------------------------------------------
__global__ void __launch_bounds__(THREADS, 2)
gemm_kernel(float* __restrict__ out) {
    const int tid = threadIdx.x;
    const int wid = tid >> 5;
    const int lid = tid & 31;

    // 16 consecutive CTAs share one A tile (L2/L1 locality on A)
    const int mtile = blockIdx.x >> 4;          // 0..255
    const int ntile = blockIdx.x & 15;          // 0..15
    const int m_base = mtile * M_TILE;
    const int n_base = ntile * N_TILE;

    // warp tiling: 2 (m) x 2 (n) warps, warp tile 64x64
    const int warp_m = wid >> 1;
    const int warp_n = wid & 1;
    const int m16w = (m_base + warp_m * 64) >> 4;   // first of 4 m16 blocks
    const int n16w = (n_base + warp_n * 64) >> 4;   // first of 4 n16 blocks

    const uint4* __restrict__ Ap = g_Xa;
    const uint4* __restrict__ Bp = g_Wb;

    float acc[4][8][4];
#pragma unroll
    for (int mi = 0; mi < 4; mi++)
#pragma unroll
        for (int ni = 0; ni < 8; ni++)
#pragma unroll
            for (int j = 0; j < 4; j++) acc[mi][ni][j] = 0.f;

    uint4 abuf[2][4];
    uint4 bbuf[2][4];

    // prime k-step 0
#pragma unroll
    for (int mi = 0; mi < 4; mi++)
        abuf[0][mi] = __ldg(&Ap[((size_t)(m16w + mi) * 16 + 0) * 32 + lid]);
#pragma unroll
    for (int p = 0; p < 4; p++)
        bbuf[0][p] = __ldg(&Bp[((size_t)(n16w + p) * 16 + 0) * 32 + lid]);

#pragma unroll
    for (int ks = 0; ks < KSTEPS; ks++) {
        const int cur = ks & 1, nxt = cur ^ 1;
        if (ks < KSTEPS - 1) {
#pragma unroll
            for (int mi = 0; mi < 4; mi++)
                abuf[nxt][mi] =
                    __ldg(&Ap[((size_t)(m16w + mi) * 16 + ks + 1) * 32 + lid]);
#pragma unroll
            for (int p = 0; p < 4; p++)
                bbuf[nxt][p] =
                    __ldg(&Bp[((size_t)(n16w + p) * 16 + ks + 1) * 32 + lid]);
        }
#pragma unroll
        for (int mi = 0; mi < 4; mi++) {
            const uint32_t* a = (const uint32_t*)&abuf[cur][mi];
#pragma unroll
            for (int p = 0; p < 4; p++) {
                mma16816(acc[mi][2 * p],     a, bbuf[cur][p].x, bbuf[cur][p].y);
                mma16816(acc[mi][2 * p + 1], a, bbuf[cur][p].z, bbuf[cur][p].w);
            }
        }
    }

    // ---- epilogue: bias + store (float2, 32B sector-complete per lane quad) ----
    const int qrow = lid >> 2;                  // 0..7
    const int qcol = (lid & 3) * 2;             // 0,2,4,6
    const int m_off = warp_m * 64;
    const int n_off = warp_n * 64;

#pragma unroll
    for (int mi = 0; mi < 4; mi++) {
        const int r0 = m_base + m_off + mi * 16 + qrow;
        float* orow0 = out + (size_t)r0 * NN + n_base;
        float* orow1 = orow0 + (size_t)8 * NN;
#pragma unroll
        for (int ni = 0; ni < 8; ni++) {
            const int col = n_off + ni * 8 + qcol;
            const float2 bv = __ldg((const float2*)(g_bsum + n_base + col));
            float2 v0 = make_float2(acc[mi][ni][0] + bv.x, acc[mi][ni][1] + bv.y);
            float2 v1 = make_float2(acc[mi][ni][2] + bv.x, acc[mi][ni][3] + bv.y);
            *(float2*)(orow0 + col) = v0;
            *(float2*)(orow1 + col) = v1;
        }
    }
}

// ---------------------------------------------------------------------------
// Launch
// ---------------------------------------------------------------------------
extern "C" void kernel_launch(void* const* d_in, const int* in_sizes, int n_in,
                              void* d_out, int out_size) {
    const float* x     = (const float*)d_in[0];
    // d_in[1]=W_gate, d_in[2]=b_gate: softmax row-sum == 1 -> unused.
    const float* W_exp = (const float*)d_in[3];
    const float* b_exp = (const float*)d_in[4];
    float* out = (float*)d_out;

    prep_kernel<<<PREP_BLOCKS, 256>>>(x, W_exp, b_exp);
    gemm_kernel<<<(Bsz / M_TILE) * (NN / N_TILE), THREADS>>>(out);
}

// round 10
// speedup vs baseline: 1.0756x; 1.0756x over previous
#include <cuda_runtime.h>
#include <cuda_fp16.h>
#include <cstdint>

// ============================================================================
// NestedMoEModel: softmax gate row-sums to 1 => gate path is a no-op.
// out[B, G*H] = x @ (sum_e W_exp)^T + sum_e b_exp
// Single GEMM M=32768, N=2048, K=256 via fp16 mma.sync (fp32 accumulate).
// PTX target is sm_103 (no 'a') -> tcgen05 unavailable; mma.sync path.
// R10: hybrid operands. A via cp.async->smem->LDSM (4 dedicated stages, no
//      ring); B via direct LDG.128 from fragment-layout g_Wb (L2-hot, no
//      barrier coupling). Halves LDS bytes per HMMA vs R6.
// ============================================================================

#define DINLINE __device__ __forceinline__

static constexpr int Bsz = 32768;
static constexpr int Dsz = 256;     // K
static constexpr int NN  = 2048;    // G*H = output cols
static constexpr int M_TILE = 128;
static constexpr int N_TILE = 128;
static constexpr int K_CHUNK = 64;                   // halves per chunk (128B rows)
static constexpr int NUM_CHUNKS = Dsz / K_CHUNK;     // 4
static constexpr int THREADS = 128;                  // 4 warps, 2x2 grid of 64x64
static constexpr int KSTEPS = Dsz / 16;              // 16

// SMEM: 4 dedicated A stages (16KB each) + bias
static constexpr int A_BYTES = M_TILE * 128;             // 16384
static constexpr int OFF_BIAS = NUM_CHUNKS * A_BYTES;    // 65536
static constexpr int SMEM_TOTAL = OFF_BIAS + N_TILE * 4; // 66048 -> 2 CTAs/SM

// Scratch (device globals: no allocations allowed)
__device__ __align__(128) __half g_Xh[Bsz * Dsz];    // 16MB fp16 x (row-major)
// g_Wb: [n16 0..127][ks 0..15][lane 0..31] -> uint4 {b_lo0,b_lo1,b_hi0,b_hi1}
//   n_lo = n16*16 + (lane>>2), n_hi = n_lo+8, k0 = ks*16 + (lane&3)*2
//   b_lo0 = w[n_lo][k0..k0+1], b_lo1 = w[n_lo][k0+8..+9], b_hi* same for n_hi
__device__ __align__(128) uint4 g_Wb[(NN / 16) * KSTEPS * 32];    // 1MB
__device__ __align__(128) float g_bsum[NN];

// ---------------------------------------------------------------------------
// helpers
// ---------------------------------------------------------------------------
DINLINE uint32_t smem_u32(const void* p) {
    uint32_t a;
    asm("{ .reg .u64 t; cvta.to.shared.u64 t, %1; cvt.u32.u64 %0, t; }"
        : "=r"(a) : "l"(p));
    return a;
}

DINLINE uint32_t pack2(float lo, float hi) {
    __half2 h = __floats2half2_rn(lo, hi);
    return *(uint32_t*)&h;
}

DINLINE void cp_async16(uint32_t saddr, const void* gaddr) {
    asm volatile("cp.async.cg.shared.global [%0], [%1], 16;"
                 :: "r"(saddr), "l"(gaddr) : "memory");
}
#define CP_COMMIT() asm volatile("cp.async.commit_group;" ::: "memory")
#define CP_WAIT(n)  asm volatile("cp.async.wait_group %0;" :: "n"(n) : "memory")

// SW128-style XOR swizzle for 128B rows (16B granularity)
#define SWZ(o) ((o) ^ (((o) >> 3) & 0x70))

DINLINE void ldsm_x4(uint32_t& r0, uint32_t& r1, uint32_t& r2, uint32_t& r3,
                     uint32_t addr) {
    asm volatile("ldmatrix.sync.aligned.m8n8.x4.shared.b16 {%0,%1,%2,%3}, [%4];"
                 : "=r"(r0), "=r"(r1), "=r"(r2), "=r"(r3) : "r"(addr));
}

DINLINE void mma16816(float* d, const uint32_t* a, uint32_t b0, uint32_t b1) {
    asm volatile(
        "mma.sync.aligned.m16n8k16.row.col.f32.f16.f16.f32 "
        "{%0,%1,%2,%3}, {%4,%5,%6,%7}, {%8,%9}, {%0,%1,%2,%3};"
        : "+f"(d[0]), "+f"(d[1]), "+f"(d[2]), "+f"(d[3])
        : "r"(a[0]), "r"(a[1]), "r"(a[2]), "r"(a[3]), "r"(b0), "r"(b1));
}

// ---------------------------------------------------------------------------
// Fused prep:
//  blocks [0,256):    Wsum (reduce 8 experts) -> g_Wb fragment layout;
//                     blocks [0,8) also compute bias sums.
//  blocks [256,2304): x -> fp16 row-major, 4 independent float4 per thread.
// ---------------------------------------------------------------------------
__global__ void __launch_bounds__(256)
prep_kernel(const float* __restrict__ X,
            const float* __restrict__ W_exp,
            const float* __restrict__ b_exp) {
    const int blk = blockIdx.x;
    const int tid = threadIdx.x;

    if (blk < 256) {
        // ---- W path: one uint4 fragment entry per thread ----
        const int entry = blk * 256 + tid;          // [0, 65536)
        const int n16  = entry >> 9;                // 0..127
        const int ks   = (entry >> 5) & 15;
        const int lane = entry & 31;
        const int n_lo = n16 * 16 + (lane >> 2);
        const int k0   = ks * 16 + (lane & 3) * 2;
        const int g    = n_lo >> 8;
        const int h_lo = n_lo & 255;

        float s[8];
#pragma unroll
        for (int j = 0; j < 8; j++) s[j] = 0.f;
#pragma unroll
        for (int e = 0; e < 8; e++) {
            const float* we = W_exp + ((size_t)(g * 8 + e) * 256) * 256;
            float2 lo_a = *(const float2*)(we + (size_t)h_lo * 256 + k0);
            float2 lo_b = *(const float2*)(we + (size_t)h_lo * 256 + k0 + 8);
            float2 hi_a = *(const float2*)(we + (size_t)(h_lo + 8) * 256 + k0);
            float2 hi_b = *(const float2*)(we + (size_t)(h_lo + 8) * 256 + k0 + 8);
            s[0] += lo_a.x; s[1] += lo_a.y;
            s[2] += lo_b.x; s[3] += lo_b.y;
            s[4] += hi_a.x; s[5] += hi_a.y;
            s[6] += hi_b.x; s[7] += hi_b.y;
        }
        uint4 v;
        v.x = pack2(s[0], s[1]);
        v.y = pack2(s[2], s[3]);
        v.z = pack2(s[4], s[5]);
        v.w = pack2(s[6], s[7]);
        g_Wb[entry] = v;

        if (blk < 8) {
            float bs = 0.f;
#pragma unroll
            for (int e = 0; e < 8; e++)
                bs += b_exp[(blk * 8 + e) * 256 + tid];
            g_bsum[blk * 256 + tid] = bs;
        }
    } else {
        // each block: 256 threads x 4 float4 = 4096 floats (MLP = 4)
        const size_t f4base = (size_t)(blk - 256) * 1024 + tid;
        const float4* src = (const float4*)X;
        float4 v[4];
#pragma unroll
        for (int j = 0; j < 4; j++) v[j] = src[f4base + j * 256];
#pragma unroll
        for (int j = 0; j < 4; j++) {
            uint2 pk;
            pk.x = pack2(v[j].x, v[j].y);
            pk.y = pack2(v[j].z, v[j].w);
            *(uint2*)(g_Xh + (f4base + j * 256) * 4) = pk;
        }
    }
}
static constexpr int PREP_BLOCKS = 256 + (Bsz * Dsz) / (256 * 16);  // 2304

// ---------------------------------------------------------------------------
// A chunk load: 128 rows x 8 x 16B = 1024 chunks -> 8 per thread
// ---------------------------------------------------------------------------
DINLINE void load_a_chunk(uint32_t astage, int m_base, int kc, int tid) {
#pragma unroll
    for (int i = 0; i < 8; i++) {
        const int idx = i * THREADS + tid;
        const int row = idx >> 3;
        const int c16 = idx & 7;
        const __half* g = g_Xh + (size_t)(m_base + row) * 256
                          + kc * K_CHUNK + c16 * 8;
        cp_async16(astage + SWZ(row * 128 + c16 * 16), g);
    }
    CP_COMMIT();
}

// A fragments for one k16 step within a chunk stage
DINLINE void load_a_frags(uint32_t astage, int m_off, int grp, int r8, int ks,
                          uint32_t a[4][4]) {
#pragma unroll
    for (int mi = 0; mi < 4; mi++) {
        const int row = m_off + mi * 16 + (grp & 1) * 8 + r8;
        const int cg  = ks * 2 + (grp >> 1);
        ldsm_x4(a[mi][0], a[mi][1], a[mi][2], a[mi][3],
                astage + SWZ(row * 128 + cg * 16));
    }
}

// B fragments for one global k16 step: 4 coalesced LDG.128
DINLINE void load_b_frags(int n16w, int lid, int ksg, uint4 b[4]) {
#pragma unroll
    for (int p = 0; p < 4; p++)
        b[p] = __ldg(&g_Wb[((size_t)(n16w + p) * 16 + ksg) * 32 + lid]);
}

DINLINE void mma_all(float acc[4][8][4], uint32_t a[4][4], uint4 b[4]) {
#pragma unroll
    for (int mi = 0; mi < 4; mi++)
#pragma unroll
        for (int p = 0; p < 4; p++) {
            mma16816(acc[mi][2 * p],     a[mi], b[p].x, b[p].y);
            mma16816(acc[mi][2 * p + 1], a[mi], b[p].z, b[p].w);
        }
}

// ---------------------------------------------------------------------------
// GEMM: out = Xh @ Wb^T + bsum
// CTA 128x128, 128 threads (4 warps, 2x2 grid, warp tile 64x64). 2 CTAs/SM.
// A: 4 dedicated cp.async stages; B: direct LDG, barrier-free.
// ---------------------------------------------------------------------------
__global__ void __launch_bounds__(THREADS, 2)
gemm_kernel(float* __restrict__ out) {
    extern __shared__ char smem[];
    const uint32_t sbase = smem_u32(smem);
    const int tid = threadIdx.x;
    const int wid = tid >> 5;
    const int lid = tid & 31;

    // 16 consecutive CTAs share one A tile (L2 locality on A)
    const int mtile = blockIdx.x >> 4;          // 0..255
    const int ntile = blockIdx.x & 15;          // 0..15
    const int m_base = mtile * M_TILE;
    const int n_base = ntile * N_TILE;

    // bias slice (made visible by the chunk-0 barrier below)
    *(float*)(smem + OFF_BIAS + tid * 4) = g_bsum[n_base + tid];

    // ---- prologue: issue all 4 A-chunk loads (dedicated stages) ----
    load_a_chunk(sbase + 0 * A_BYTES, m_base, 0, tid);
    load_a_chunk(sbase + 1 * A_BYTES, m_base, 1, tid);
    load_a_chunk(sbase + 2 * A_BYTES, m_base, 2, tid);
    load_a_chunk(sbase + 3 * A_BYTES, m_base, 3, tid);

    // warp tiling: 2 (m) x 2 (n) warps, warp tile 64x64
    const int warp_m = wid >> 1;
    const int warp_n = wid & 1;
    const int m_off = warp_m * 64;
    const int n_off = warp_n * 64;
    const int n16w = (n_base + n_off) >> 4;
    const int grp = lid >> 3;                   // 0..3
    const int r8  = lid & 7;

    float acc[4][8][4];
#pragma unroll
    for (int mi = 0; mi < 4; mi++)
#pragma unroll
        for (int ni = 0; ni < 8; ni++)
#pragma unroll
            for (int j = 0; j < 4; j++) acc[mi][ni][j] = 0.f;

    uint32_t abuf[2][4][4];
    uint4 bbuf[2][4];

    // B k-step 0 prefetch (no barrier needed)
    load_b_frags(n16w, lid, 0, bbuf[0]);

    // chunk 0 A ready; prime A ks0
    CP_WAIT(3);
    __syncthreads();
    load_a_frags(sbase, m_off, grp, r8, 0, abuf[0]);

    // ---- main loop over K chunks ----
#pragma unroll
    for (int kc = 0; kc < NUM_CHUNKS; kc++) {
        const uint32_t astage = sbase + kc * A_BYTES;

#pragma unroll
        for (int ks = 0; ks < 4; ks++) {
            const int cur = (kc * 4 + ks) & 1, nxt = cur ^ 1;
            const int ksg = kc * 4 + ks;

            if (ks < 3) {
                // next frags from same stage
                load_b_frags(n16w, lid, ksg + 1, bbuf[nxt]);
                load_a_frags(astage, m_off, grp, r8, ks + 1, abuf[nxt]);
            } else if (kc < NUM_CHUNKS - 1) {
                // boundary: B prefetch is barrier-free; then wait next A stage
                load_b_frags(n16w, lid, ksg + 1, bbuf[nxt]);
                if (kc == 0) CP_WAIT(2);
                else if (kc == 1) CP_WAIT(1);
                else CP_WAIT(0);
                __syncthreads();
                load_a_frags(sbase + (kc + 1) * A_BYTES, m_off, grp, r8, 0,
                             abuf[nxt]);
            }
            mma_all(acc, abuf[cur], bbuf[cur]);
        }
    }

    // ---- epilogue: bias + store (float2, 32B sector-complete per lane quad) ----
    const float* sbias = (const float*)(smem + OFF_BIAS);
    const int qrow = lid >> 2;                  // 0..7
    const int qcol = (lid & 3) * 2;             // 0,2,4,6

#pragma unroll
    for (int mi = 0; mi < 4; mi++) {
        const int r0 = m_base + m_off + mi * 16 + qrow;
        float* orow0 = out + (size_t)r0 * NN + n_base;
        float* orow1 = orow0 + (size_t)8 * NN;
#pragma unroll
        for (int ni = 0; ni < 8; ni++) {
            const int col = n_off + ni * 8 + qcol;
            const float b0 = sbias[col], b1 = sbias[col + 1];
            float2 v0 = make_float2(acc[mi][ni][0] + b0, acc[mi][ni][1] + b1);
            float2 v1 = make_float2(acc[mi][ni][2] + b0, acc[mi][ni][3] + b1);
            *(float2*)(orow0 + col) = v0;
            *(float2*)(orow1 + col) = v1;
        }
    }
}

// ---------------------------------------------------------------------------
// Launch
// ---------------------------------------------------------------------------
extern "C" void kernel_launch(void* const* d_in, const int* in_sizes, int n_in,
                              void* d_out, int out_size) {
    const float* x     = (const float*)d_in[0];
    // d_in[1]=W_gate, d_in[2]=b_gate: softmax row-sum == 1 -> unused.
    const float* W_exp = (const float*)d_in[3];
    const float* b_exp = (const float*)d_in[4];
    float* out = (float*)d_out;

    cudaFuncSetAttribute(gemm_kernel,
                         cudaFuncAttributeMaxDynamicSharedMemorySize, SMEM_TOTAL);

    prep_kernel<<<PREP_BLOCKS, 256>>>(x, W_exp, b_exp);
    gemm_kernel<<<(Bsz / M_TILE) * (NN / N_TILE), THREADS, SMEM_TOTAL>>>(out);
}